// round 3
// baseline (speedup 1.0000x reference)
#include <cuda_runtime.h>

#define NFFT 512
#define ROWS_PER_BLK 2
#define THREADS (ROWS_PER_BLK * 64)
#define PADDED 576   /* 512 + 512/8 : padding keeps every phase conflict-free */

struct cplx { float re, im; };

__device__ __forceinline__ cplx cadd(cplx a, cplx b) { return {a.re + b.re, a.im + b.im}; }
__device__ __forceinline__ cplx csub(cplx a, cplx b) { return {a.re - b.re, a.im - b.im}; }
__device__ __forceinline__ cplx cmul(cplx a, cplx b) {
    return {fmaf(a.re, b.re, -a.im * b.im), fmaf(a.re, b.im, a.im * b.re)};
}
// multiply by -i : (x + iy)*(-i) = y - ix
__device__ __forceinline__ cplx mul_mi(cplx a) { return {a.im, -a.re}; }

// Forward DFT-8: b[k] = sum_r a[r] * exp(-2*pi*i*r*k/8)
__device__ __forceinline__ void dft8(const cplx* a, cplx* b) {
    const float S = 0.70710678118654752440f;
    cplx e0 = cadd(a[0], a[4]), e1 = csub(a[0], a[4]);
    cplx e2 = cadd(a[2], a[6]), e3 = csub(a[2], a[6]);
    cplx E0 = cadd(e0, e2), E2 = csub(e0, e2);
    cplx m3 = mul_mi(e3);
    cplx E1 = cadd(e1, m3), E3 = csub(e1, m3);
    cplx o0 = cadd(a[1], a[5]), o1 = csub(a[1], a[5]);
    cplx o2 = cadd(a[3], a[7]), o3 = csub(a[3], a[7]);
    cplx O0 = cadd(o0, o2), O2 = csub(o0, o2);
    cplx n3 = mul_mi(o3);
    cplx O1 = cadd(o1, n3), O3 = csub(o1, n3);
    cplx O1w = { S * (O1.re + O1.im), S * (O1.im - O1.re) };
    cplx O2w = mul_mi(O2);
    cplx O3w = { S * (O3.im - O3.re), -S * (O3.re + O3.im) };
    b[0] = cadd(E0, O0);  b[4] = csub(E0, O0);
    b[1] = cadd(E1, O1w); b[5] = csub(E1, O1w);
    b[2] = cadd(E2, O2w); b[6] = csub(E2, O2w);
    b[3] = cadd(E3, O3w); b[7] = csub(E3, O3w);
}

__device__ __forceinline__ int pad(int idx) { return idx + (idx >> 3); }

// per-row barrier: 64 threads, ids 1..ROWS_PER_BLK
__device__ __forceinline__ void row_bar(int r) {
    asm volatile("bar.sync %0, 64;" :: "r"(r + 1) : "memory");
}

__global__ __launch_bounds__(THREADS, 12)
void range_fft512_kernel(const float* __restrict__ xre,
                         const float* __restrict__ xim,
                         float2* __restrict__ out,
                         int nrows)
{
    __shared__ float2 buf[ROWS_PER_BLK][PADDED];

    const int tid      = threadIdx.x;
    const int r_in_blk = tid >> 6;
    const int lane     = tid & 63;
    long long row = (long long)blockIdx.x * ROWS_PER_BLK + r_in_blk;
    const bool valid = row < nrows;
    long long srow = valid ? row : 0;   // clamp loads; all threads must reach barriers

    const float* xr = xre + srow * NFFT;
    const float* xi = xim + srow * NFFT;

    const float TWO_PI_OVER_N = 6.28318530717958647692f / (float)NFFT;

    // ---- stage 0: n=512, s=1. p = lane. gmem -> buf ----
    {
        cplx a[8], b[8];
        #pragma unroll
        for (int r = 0; r < 8; r++) {
            a[r].re = __ldcs(xr + lane + 64 * r);
            a[r].im = __ldcs(xi + lane + 64 * r);
        }
        dft8(a, b);
        const int p = lane;
        // base twiddle exp(-2*pi*i*p/512), powered up by running multiply
        float s1, c1;
        __sincosf(-TWO_PI_OVER_N * (float)p, &s1, &c1);
        cplx t1 = {c1, s1}, t = t1;
        buf[r_in_blk][pad(8 * p + 0)] = make_float2(b[0].re, b[0].im);
        #pragma unroll
        for (int k = 1; k < 8; k++) {
            cplx c = cmul(b[k], t);
            buf[r_in_blk][pad(8 * p + k)] = make_float2(c.re, c.im);
            if (k < 7) t = cmul(t, t1);
        }
    }
    row_bar(r_in_blk);

    // ---- stage 1: n=64, s=8. p = lane>>3, q = lane&7. buf -> regs -> buf ----
    {
        const int p = lane >> 3, q = lane & 7;
        cplx a[8], b[8];
        #pragma unroll
        for (int r = 0; r < 8; r++) {
            float2 v = buf[r_in_blk][pad(lane + 64 * r)];   // q + 8p == lane
            a[r] = {v.x, v.y};
        }
        row_bar(r_in_blk);   // all reads done before in-place overwrite
        dft8(a, b);
        // base twiddle exp(-2*pi*i*p/64) = exp(-2*pi*i*(8p)/512)
        float s1, c1;
        __sincosf(-TWO_PI_OVER_N * (float)(8 * p), &s1, &c1);
        cplx t1 = {c1, s1}, t = t1;
        buf[r_in_blk][pad(q + 64 * p + 0)] = make_float2(b[0].re, b[0].im);
        #pragma unroll
        for (int k = 1; k < 8; k++) {
            cplx c = cmul(b[k], t);
            buf[r_in_blk][pad(q + 64 * p + 8 * k)] = make_float2(c.re, c.im);
            if (k < 7) t = cmul(t, t1);
        }
    }
    row_bar(r_in_blk);

    // ---- stage 2: n=8, s=64. twiddle==1. buf -> gmem ----
    {
        cplx a[8], b[8];
        #pragma unroll
        for (int r = 0; r < 8; r++) {
            float2 v = buf[r_in_blk][pad(lane + 64 * r)];
            a[r] = {v.x, v.y};
        }
        dft8(a, b);
        if (valid) {
            float2* o = out + row * NFFT;      // interleaved (re, im) = stack(..., -1)
            #pragma unroll
            for (int k = 0; k < 8; k++)
                __stcs(o + lane + 64 * k, make_float2(b[k].re, b[k].im));
        }
    }
}

extern "C" void kernel_launch(void* const* d_in, const int* in_sizes, int n_in,
                              void* d_out, int out_size) {
    const float* xre = (const float*)d_in[0];
    const float* xim = (const float*)d_in[1];
    (void)n_in; (void)out_size;

    int nrows = in_sizes[0] / NFFT;   // 8*16*256 = 32768
    int grid  = (nrows + ROWS_PER_BLK - 1) / ROWS_PER_BLK;
    range_fft512_kernel<<<grid, THREADS>>>(xre, xim, (float2*)d_out, nrows);
}

// round 4
// speedup vs baseline: 1.2053x; 1.2053x over previous
#include <cuda_runtime.h>

#define NFFT 512
#define ROWS_PER_BLK 2
#define THREADS (ROWS_PER_BLK * 64)
#define PADDED 576   /* 512 + 512/8 : padding keeps every phase conflict-light */

struct cplx { float re, im; };

__device__ __forceinline__ cplx cadd(cplx a, cplx b) { return {a.re + b.re, a.im + b.im}; }
__device__ __forceinline__ cplx csub(cplx a, cplx b) { return {a.re - b.re, a.im - b.im}; }
__device__ __forceinline__ cplx cmul(cplx a, cplx b) {
    return {fmaf(a.re, b.re, -a.im * b.im), fmaf(a.re, b.im, a.im * b.re)};
}
// multiply by -i : (x + iy)*(-i) = y - ix
__device__ __forceinline__ cplx mul_mi(cplx a) { return {a.im, -a.re}; }

// Forward DFT-8: b[k] = sum_r a[r] * exp(-2*pi*i*r*k/8)
__device__ __forceinline__ void dft8(const cplx* a, cplx* b) {
    const float S = 0.70710678118654752440f;
    cplx e0 = cadd(a[0], a[4]), e1 = csub(a[0], a[4]);
    cplx e2 = cadd(a[2], a[6]), e3 = csub(a[2], a[6]);
    cplx E0 = cadd(e0, e2), E2 = csub(e0, e2);
    cplx m3 = mul_mi(e3);
    cplx E1 = cadd(e1, m3), E3 = csub(e1, m3);
    cplx o0 = cadd(a[1], a[5]), o1 = csub(a[1], a[5]);
    cplx o2 = cadd(a[3], a[7]), o3 = csub(a[3], a[7]);
    cplx O0 = cadd(o0, o2), O2 = csub(o0, o2);
    cplx n3 = mul_mi(o3);
    cplx O1 = cadd(o1, n3), O3 = csub(o1, n3);
    cplx O1w = { S * (O1.re + O1.im), S * (O1.im - O1.re) };
    cplx O2w = mul_mi(O2);
    cplx O3w = { S * (O3.im - O3.re), -S * (O3.re + O3.im) };
    b[0] = cadd(E0, O0);  b[4] = csub(E0, O0);
    b[1] = cadd(E1, O1w); b[5] = csub(E1, O1w);
    b[2] = cadd(E2, O2w); b[6] = csub(E2, O2w);
    b[3] = cadd(E3, O3w); b[7] = csub(E3, O3w);
}

__device__ __forceinline__ int pad(int idx) { return idx + (idx >> 3); }

__global__ __launch_bounds__(THREADS, 12)
void range_fft512_kernel(const float* __restrict__ xre,
                         const float* __restrict__ xim,
                         float2* __restrict__ out,
                         int nrows)
{
    __shared__ float2 buf[ROWS_PER_BLK][PADDED];

    const int tid      = threadIdx.x;
    const int r_in_blk = tid >> 6;
    const int lane     = tid & 63;
    long long row = (long long)blockIdx.x * ROWS_PER_BLK + r_in_blk;
    const bool valid = row < nrows;
    long long srow = valid ? row : 0;   // clamp loads; all threads must reach barriers

    const float* xr = xre + srow * NFFT;
    const float* xi = xim + srow * NFFT;

    const float TWO_PI_OVER_N = 6.28318530717958647692f / (float)NFFT;

    // ---- stage 0: n=512, s=1. p = lane. gmem -> buf ----
    {
        cplx a[8], b[8];
        #pragma unroll
        for (int r = 0; r < 8; r++) {
            a[r].re = __ldcs(xr + lane + 64 * r);
            a[r].im = __ldcs(xi + lane + 64 * r);
        }
        dft8(a, b);
        const int p = lane;
        // base twiddle exp(-2*pi*i*p/512), powered up by running complex multiply
        float s1, c1;
        __sincosf(-TWO_PI_OVER_N * (float)p, &s1, &c1);
        cplx t1 = {c1, s1}, t = t1;
        buf[r_in_blk][pad(8 * p + 0)] = make_float2(b[0].re, b[0].im);
        #pragma unroll
        for (int k = 1; k < 8; k++) {
            cplx c = cmul(b[k], t);
            buf[r_in_blk][pad(8 * p + k)] = make_float2(c.re, c.im);
            if (k < 7) t = cmul(t, t1);
        }
    }
    __syncthreads();

    // ---- stage 1: n=64, s=8. p = lane>>3, q = lane&7. buf -> regs -> buf ----
    {
        const int p = lane >> 3, q = lane & 7;
        cplx a[8], b[8];
        #pragma unroll
        for (int r = 0; r < 8; r++) {
            float2 v = buf[r_in_blk][pad(lane + 64 * r)];   // q + 8p == lane
            a[r] = {v.x, v.y};
        }
        __syncthreads();   // all reads done before in-place overwrite
        dft8(a, b);
        // base twiddle exp(-2*pi*i*p/64) = exp(-2*pi*i*(8p)/512)
        float s1, c1;
        __sincosf(-TWO_PI_OVER_N * (float)(8 * p), &s1, &c1);
        cplx t1 = {c1, s1}, t = t1;
        buf[r_in_blk][pad(q + 64 * p + 0)] = make_float2(b[0].re, b[0].im);
        #pragma unroll
        for (int k = 1; k < 8; k++) {
            cplx c = cmul(b[k], t);
            buf[r_in_blk][pad(q + 64 * p + 8 * k)] = make_float2(c.re, c.im);
            if (k < 7) t = cmul(t, t1);
        }
    }
    __syncthreads();

    // ---- stage 2: n=8, s=64. twiddle==1. buf -> gmem ----
    {
        cplx a[8], b[8];
        #pragma unroll
        for (int r = 0; r < 8; r++) {
            float2 v = buf[r_in_blk][pad(lane + 64 * r)];
            a[r] = {v.x, v.y};
        }
        dft8(a, b);
        if (valid) {
            float2* o = out + row * NFFT;      // interleaved (re, im) = stack(..., -1)
            #pragma unroll
            for (int k = 0; k < 8; k++)
                __stcs(o + lane + 64 * k, make_float2(b[k].re, b[k].im));
        }
    }
}

extern "C" void kernel_launch(void* const* d_in, const int* in_sizes, int n_in,
                              void* d_out, int out_size) {
    const float* xre = (const float*)d_in[0];
    const float* xim = (const float*)d_in[1];
    (void)n_in; (void)out_size;

    int nrows = in_sizes[0] / NFFT;   // 8*16*256 = 32768
    int grid  = (nrows + ROWS_PER_BLK - 1) / ROWS_PER_BLK;
    range_fft512_kernel<<<grid, THREADS>>>(xre, xim, (float2*)d_out, nrows);
}

// round 5
// speedup vs baseline: 1.2354x; 1.0250x over previous
#include <cuda_runtime.h>

#define NFFT 512
#define THREADS 64
#define PADDED 576   /* 512 + 512/8 : padding keeps every phase conflict-light */

struct cplx { float re, im; };

__device__ __forceinline__ cplx cadd(cplx a, cplx b) { return {a.re + b.re, a.im + b.im}; }
__device__ __forceinline__ cplx csub(cplx a, cplx b) { return {a.re - b.re, a.im - b.im}; }
__device__ __forceinline__ cplx cmul(cplx a, cplx b) {
    return {fmaf(a.re, b.re, -a.im * b.im), fmaf(a.re, b.im, a.im * b.re)};
}
// multiply by -i : (x + iy)*(-i) = y - ix
__device__ __forceinline__ cplx mul_mi(cplx a) { return {a.im, -a.re}; }

// Forward DFT-8: b[k] = sum_r a[r] * exp(-2*pi*i*r*k/8)
__device__ __forceinline__ void dft8(const cplx* a, cplx* b) {
    const float S = 0.70710678118654752440f;
    cplx e0 = cadd(a[0], a[4]), e1 = csub(a[0], a[4]);
    cplx e2 = cadd(a[2], a[6]), e3 = csub(a[2], a[6]);
    cplx E0 = cadd(e0, e2), E2 = csub(e0, e2);
    cplx m3 = mul_mi(e3);
    cplx E1 = cadd(e1, m3), E3 = csub(e1, m3);
    cplx o0 = cadd(a[1], a[5]), o1 = csub(a[1], a[5]);
    cplx o2 = cadd(a[3], a[7]), o3 = csub(a[3], a[7]);
    cplx O0 = cadd(o0, o2), O2 = csub(o0, o2);
    cplx n3 = mul_mi(o3);
    cplx O1 = cadd(o1, n3), O3 = csub(o1, n3);
    cplx O1w = { S * (O1.re + O1.im), S * (O1.im - O1.re) };
    cplx O2w = mul_mi(O2);
    cplx O3w = { S * (O3.im - O3.re), -S * (O3.re + O3.im) };
    b[0] = cadd(E0, O0);  b[4] = csub(E0, O0);
    b[1] = cadd(E1, O1w); b[5] = csub(E1, O1w);
    b[2] = cadd(E2, O2w); b[6] = csub(E2, O2w);
    b[3] = cadd(E3, O3w); b[7] = csub(E3, O3w);
}

__device__ __forceinline__ int pad(int idx) { return idx + (idx >> 3); }

// twiddle powers t^1..t^7 with shallow dependency tree (depth 3)
__device__ __forceinline__ void tw_powers(cplx t1, cplx* t) {
    t[1] = t1;
    t[2] = cmul(t1, t1);
    t[3] = cmul(t[2], t1);
    t[4] = cmul(t[2], t[2]);
    t[5] = cmul(t[2], t[3]);
    t[6] = cmul(t[3], t[3]);
    t[7] = cmul(t[3], t[4]);
}

__global__ __launch_bounds__(THREADS)
void range_fft512_kernel(const float* __restrict__ xre,
                         const float* __restrict__ xim,
                         float2* __restrict__ out,
                         int nrows)
{
    __shared__ float2 buf[PADDED];

    const int lane = threadIdx.x;          // 0..63
    long long row = blockIdx.x;
    const bool valid = row < nrows;
    long long srow = valid ? row : 0;

    const float* xr = xre + srow * NFFT;
    const float* xi = xim + srow * NFFT;

    const float TWO_PI_OVER_N = 6.28318530717958647692f / (float)NFFT;

    // ---- stage 0: n=512, s=1. p = lane. gmem -> buf ----
    {
        cplx a[8], b[8];
        #pragma unroll
        for (int r = 0; r < 8; r++) {
            a[r].re = __ldcs(xr + lane + 64 * r);
            a[r].im = __ldcs(xi + lane + 64 * r);
        }
        dft8(a, b);
        const int p = lane;
        float s1, c1;
        __sincosf(-TWO_PI_OVER_N * (float)p, &s1, &c1);
        cplx t[8];
        tw_powers(cplx{c1, s1}, t);
        buf[pad(8 * p + 0)] = make_float2(b[0].re, b[0].im);
        #pragma unroll
        for (int k = 1; k < 8; k++) {
            cplx c = cmul(b[k], t[k]);
            buf[pad(8 * p + k)] = make_float2(c.re, c.im);
        }
    }
    __syncthreads();   // 2-warp barrier: per-row sync, cheap

    // ---- stage 1: n=64, s=8. p = lane>>3, q = lane&7. buf -> regs -> buf ----
    {
        const int p = lane >> 3, q = lane & 7;
        cplx a[8], b[8];
        #pragma unroll
        for (int r = 0; r < 8; r++) {
            float2 v = buf[pad(lane + 64 * r)];   // q + 8p == lane
            a[r] = {v.x, v.y};
        }
        __syncthreads();   // all reads done before in-place overwrite
        dft8(a, b);
        float s1, c1;
        __sincosf(-TWO_PI_OVER_N * (float)(8 * p), &s1, &c1);
        cplx t[8];
        tw_powers(cplx{c1, s1}, t);
        buf[pad(q + 64 * p + 0)] = make_float2(b[0].re, b[0].im);
        #pragma unroll
        for (int k = 1; k < 8; k++) {
            cplx c = cmul(b[k], t[k]);
            buf[pad(q + 64 * p + 8 * k)] = make_float2(c.re, c.im);
        }
    }
    __syncthreads();

    // ---- stage 2: n=8, s=64. twiddle==1. buf -> gmem ----
    {
        cplx a[8], b[8];
        #pragma unroll
        for (int r = 0; r < 8; r++) {
            float2 v = buf[pad(lane + 64 * r)];
            a[r] = {v.x, v.y};
        }
        dft8(a, b);
        if (valid) {
            float2* o = out + row * NFFT;      // interleaved (re, im) = stack(..., -1)
            #pragma unroll
            for (int k = 0; k < 8; k++)
                __stcs(o + lane + 64 * k, make_float2(b[k].re, b[k].im));
        }
    }
}

extern "C" void kernel_launch(void* const* d_in, const int* in_sizes, int n_in,
                              void* d_out, int out_size) {
    const float* xre = (const float*)d_in[0];
    const float* xim = (const float*)d_in[1];
    (void)n_in; (void)out_size;

    int nrows = in_sizes[0] / NFFT;   // 8*16*256 = 32768
    range_fft512_kernel<<<nrows, THREADS>>>(xre, xim, (float2*)d_out, nrows);
}

// round 6
// speedup vs baseline: 1.3204x; 1.0689x over previous
#include <cuda_runtime.h>

#define NFFT 512
#define THREADS 64
#define CHUNK 4      /* rows per block, software-pipelined */
#define PADDED 576   /* 512 + 512/8 : padding keeps every phase conflict-light */

struct cplx { float re, im; };

__device__ __forceinline__ cplx cadd(cplx a, cplx b) { return {a.re + b.re, a.im + b.im}; }
__device__ __forceinline__ cplx csub(cplx a, cplx b) { return {a.re - b.re, a.im - b.im}; }
__device__ __forceinline__ cplx cmul(cplx a, cplx b) {
    return {fmaf(a.re, b.re, -a.im * b.im), fmaf(a.re, b.im, a.im * b.re)};
}
// multiply by -i : (x + iy)*(-i) = y - ix
__device__ __forceinline__ cplx mul_mi(cplx a) { return {a.im, -a.re}; }

// Forward DFT-8: b[k] = sum_r a[r] * exp(-2*pi*i*r*k/8)
__device__ __forceinline__ void dft8(const cplx* a, cplx* b) {
    const float S = 0.70710678118654752440f;
    cplx e0 = cadd(a[0], a[4]), e1 = csub(a[0], a[4]);
    cplx e2 = cadd(a[2], a[6]), e3 = csub(a[2], a[6]);
    cplx E0 = cadd(e0, e2), E2 = csub(e0, e2);
    cplx m3 = mul_mi(e3);
    cplx E1 = cadd(e1, m3), E3 = csub(e1, m3);
    cplx o0 = cadd(a[1], a[5]), o1 = csub(a[1], a[5]);
    cplx o2 = cadd(a[3], a[7]), o3 = csub(a[3], a[7]);
    cplx O0 = cadd(o0, o2), O2 = csub(o0, o2);
    cplx n3 = mul_mi(o3);
    cplx O1 = cadd(o1, n3), O3 = csub(o1, n3);
    cplx O1w = { S * (O1.re + O1.im), S * (O1.im - O1.re) };
    cplx O2w = mul_mi(O2);
    cplx O3w = { S * (O3.im - O3.re), -S * (O3.re + O3.im) };
    b[0] = cadd(E0, O0);  b[4] = csub(E0, O0);
    b[1] = cadd(E1, O1w); b[5] = csub(E1, O1w);
    b[2] = cadd(E2, O2w); b[6] = csub(E2, O2w);
    b[3] = cadd(E3, O3w); b[7] = csub(E3, O3w);
}

__device__ __forceinline__ int pad(int idx) { return idx + (idx >> 3); }

// twiddle powers t^1..t^7 with shallow dependency tree (depth 3)
__device__ __forceinline__ void tw_powers(cplx t1, cplx* t) {
    t[1] = t1;
    t[2] = cmul(t1, t1);
    t[3] = cmul(t[2], t1);
    t[4] = cmul(t[2], t[2]);
    t[5] = cmul(t[2], t[3]);
    t[6] = cmul(t[3], t[3]);
    t[7] = cmul(t[3], t[4]);
}

__global__ __launch_bounds__(THREADS)
void range_fft512_kernel(const float* __restrict__ xre,
                         const float* __restrict__ xim,
                         float2* __restrict__ out,
                         int nrows)
{
    __shared__ float2 bufA[PADDED];
    __shared__ float2 bufB[PADDED];

    const int lane = threadIdx.x;          // 0..63
    const long long base = (long long)blockIdx.x * CHUNK;

    const float TWO_PI_OVER_N = 6.28318530717958647692f / (float)NFFT;

    // row-invariant twiddle bases (hoisted)
    float s0, c0, s1b, c1b;
    __sincosf(-TWO_PI_OVER_N * (float)lane, &s0, &c0);           // stage-0 base, p = lane
    __sincosf(-TWO_PI_OVER_N * (float)(8 * (lane >> 3)), &s1b, &c1b);  // stage-1 base, p = lane>>3

    // prologue: load row 0
    float cr[8], ci[8];
    {
        long long r0 = base < nrows ? base : 0;
        const float* xr = xre + r0 * NFFT;
        const float* xi = xim + r0 * NFFT;
        #pragma unroll
        for (int r = 0; r < 8; r++) {
            cr[r] = __ldcs(xr + lane + 64 * r);
            ci[r] = __ldcs(xi + lane + 64 * r);
        }
    }

    #pragma unroll
    for (int rr = 0; rr < CHUNK; rr++) {
        long long row = base + rr;
        const bool valid = row < nrows;

        // prefetch next row while this row computes
        float nr[8], ni[8];
        if (rr + 1 < CHUNK) {
            long long nrow = (base + rr + 1) < nrows ? (base + rr + 1) : 0;
            const float* xr = xre + nrow * NFFT;
            const float* xi = xim + nrow * NFFT;
            #pragma unroll
            for (int r = 0; r < 8; r++) {
                nr[r] = __ldcs(xr + lane + 64 * r);
                ni[r] = __ldcs(xi + lane + 64 * r);
            }
        }

        // ---- stage 0: n=512, s=1. p = lane. regs -> bufA ----
        {
            cplx a[8], b[8];
            #pragma unroll
            for (int r = 0; r < 8; r++) a[r] = {cr[r], ci[r]};
            dft8(a, b);
            const int p = lane;
            cplx t[8];
            tw_powers(cplx{c0, s0}, t);
            bufA[pad(8 * p + 0)] = make_float2(b[0].re, b[0].im);
            #pragma unroll
            for (int k = 1; k < 8; k++) {
                cplx c = cmul(b[k], t[k]);
                bufA[pad(8 * p + k)] = make_float2(c.re, c.im);
            }
        }
        __syncthreads();   // bufA ready (also: everyone done reading bufB of prev row)

        // ---- stage 1: n=64, s=8. p = lane>>3, q = lane&7. bufA -> bufB ----
        {
            const int p = lane >> 3, q = lane & 7;
            cplx a[8], b[8];
            #pragma unroll
            for (int r = 0; r < 8; r++) {
                float2 v = bufA[pad(lane + 64 * r)];   // q + 8p == lane
                a[r] = {v.x, v.y};
            }
            dft8(a, b);
            cplx t[8];
            tw_powers(cplx{c1b, s1b}, t);
            bufB[pad(q + 64 * p + 0)] = make_float2(b[0].re, b[0].im);
            #pragma unroll
            for (int k = 1; k < 8; k++) {
                cplx c = cmul(b[k], t[k]);
                bufB[pad(q + 64 * p + 8 * k)] = make_float2(c.re, c.im);
            }
        }
        __syncthreads();   // bufB ready (also: everyone done reading bufA)

        // ---- stage 2: n=8, s=64. twiddle==1. bufB -> gmem ----
        {
            cplx a[8], b[8];
            #pragma unroll
            for (int r = 0; r < 8; r++) {
                float2 v = bufB[pad(lane + 64 * r)];
                a[r] = {v.x, v.y};
            }
            dft8(a, b);
            if (valid) {
                float2* o = out + row * NFFT;      // interleaved (re, im)
                #pragma unroll
                for (int k = 0; k < 8; k++)
                    __stcs(o + lane + 64 * k, make_float2(b[k].re, b[k].im));
            }
        }

        // rotate prefetch into current
        if (rr + 1 < CHUNK) {
            #pragma unroll
            for (int r = 0; r < 8; r++) { cr[r] = nr[r]; ci[r] = ni[r]; }
        }
    }
}

extern "C" void kernel_launch(void* const* d_in, const int* in_sizes, int n_in,
                              void* d_out, int out_size) {
    const float* xre = (const float*)d_in[0];
    const float* xim = (const float*)d_in[1];
    (void)n_in; (void)out_size;

    int nrows = in_sizes[0] / NFFT;   // 8*16*256 = 32768
    int grid  = (nrows + CHUNK - 1) / CHUNK;
    range_fft512_kernel<<<grid, THREADS>>>(xre, xim, (float2*)d_out, nrows);
}